// round 11
// baseline (speedup 1.0000x reference)
#include <cuda_runtime.h>

// WENO Black-Scholes stepper, M=80 (81 nodes), 26 Euler steps.
// Each timestep is affine in u: u_{n+1}[k] = sum_{j=-3}^{+2} C_j[k] * u[k+j],
// with C precomputed once from the fixed WENO weights. Lane l owns nodes
// {3l, 3l+1, 3l+2} (lanes 0..26). All boundary handling folded into the
// coefficients (zero rows / right-ghost fold); loop = 5 shuffles + 18 FMAs
// + 1 select per step. Weight loads are issued FIRST so the single cold
// memory wave overlaps the MUFU init and constant setup.
// (Best-measured configuration: r9 @ 6.56 us; r10's chain-split variant was
//  noise-worse, reverted.)

#define N_STEPS 26
#define FULLM 0xFFFFFFFFu

__global__ void __launch_bounds__(32, 1)
weno_bs_kernel(const float* __restrict__ om5,   // (80,3) row-major
               const float* __restrict__ om6,   // (79,3) row-major
               float* __restrict__ out)         // 81 floats
{
    const int l = threadIdx.x;
    const bool act = (l <= 26);

    // ---- issue all weight loads immediately (overlap memory with init math) ----
    // w5 rows 3l-1 .. 3l+2 -> p[0..3][0..2];  w6 rows 3l-1 .. 3l+1 -> r[0..2][..]
    float p[4][3] = {{0}}, r[3][3] = {{0}};
    if (act) {
        #pragma unroll
        for (int j = 0; j < 4; ++j) {
            int row = 3 * l - 1 + j;
            if (row >= 0 && row < 80) {
                p[j][0] = om5[3 * row]; p[j][1] = om5[3 * row + 1]; p[j][2] = om5[3 * row + 2];
            }
        }
        #pragma unroll
        for (int j = 0; j < 3; ++j) {
            int row = 3 * l - 1 + j;
            if (row >= 0 && row < 79) {
                r[j][0] = om6[3 * row]; r[j][1] = om6[3 * row + 1]; r[j][2] = om6[3 * row + 2];
            }
        }
    }

    const float H     = 0.09375f;                 // exact in fp32
    const float DT    = (float)(1.0 / 26.0);
    const float g1    = DT * 0.055f / H;          // DT*ADV/H
    const float g2    = DT * 0.045f / (H * H);    // DT*0.5*sigma^2/H^2
    const float decay = 1.0f - DT * 0.1f;

    // ---- init u0 while loads are in flight (one expf chain per lane) ----
    float a = 0.f, b = 0.f, c = 0.f;
    {
        const float EH = expf(H);
        float ea = expf(fmaf((float)(3 * l), H, -6.0f));
        float eb = ea * EH;
        float ec = eb * EH;
        a = fmaxf(fmaf(50.0f, ea, -50.0f), 0.0f);
        b = fmaxf(fmaf(50.0f, eb, -50.0f), 0.0f);
        c = fmaxf(fmaf(50.0f, ec, -50.0f), 0.0f);
        if (!act) { a = b = c = 0.f; }
    }

    // BC recurrence constants (independent of loads)
    const float E0  = expf(-0.1f * DT);
    const float S_R = 50.0f * expf(1.5f);
    float e = 1.0f;
    const bool is_bc = (l == 26);

    // ---- fused per-node 6-tap coefficients (once loads land) ----
    float Ca[6], Cb[6], Cc[6];
    {
        const float i6 = 1.0f / 6.0f;
        #pragma unroll
        for (int n = 0; n < 3; ++n) {
            const float* P = p[n + 1];   // w5 row k
            const float* Q = p[n];       // w5 row k-1
            const float* R = r[n];       // w6 row k-1
            float A_2 = (2.0f * P[0]) * i6;
            float A_1 = (-7.0f * P[0] - P[1]) * i6;
            float A0  = (11.0f * P[0] + 5.0f * P[1] + 2.0f * P[2]) * i6;
            float A1  = (2.0f * P[1] + 5.0f * P[2]) * i6;
            float A2  = (-P[2]) * i6;
            float B_3 = (2.0f * Q[0]) * i6;
            float B_2 = (-7.0f * Q[0] - Q[1]) * i6;
            float B_1 = (11.0f * Q[0] + 5.0f * Q[1] + 2.0f * Q[2]) * i6;
            float B0  = (2.0f * Q[1] + 5.0f * Q[2]) * i6;
            float B1  = (-Q[2]) * i6;
            float C0 = -g1 * B_3;
            float C1 = g1 * (A_2 - B_2) + g2 * R[0];
            float C2 = g1 * (A_1 - B_1) + g2 * (R[1] - 2.0f * R[0]);
            float C3 = g1 * (A0 - B0)   + g2 * (R[0] - 2.0f * R[1] + R[2]) + decay;
            float C4 = g1 * (A1 - B1)   + g2 * (R[1] - 2.0f * R[2]);
            float C5 = g1 * A2          + g2 * R[2];
            float* C = (n == 0) ? Ca : (n == 1) ? Cb : Cc;
            C[0] = C0; C[1] = C1; C[2] = C2; C[3] = C3; C[4] = C4; C[5] = C5;
        }
    }

    // ---- fold boundary conditions into coefficients ----
    if (l == 0) {
        #pragma unroll
        for (int j = 0; j < 6; ++j) Ca[j] = 0.0f;        // node 0 pinned to 0
        Cb[0] = 0.0f; Cb[1] = 0.0f;                      // left ghosts == 0
        Cc[0] = 0.0f;
    }
    if (l == 26) {
        Cb[3] -= Cb[5];                                  // u[81] = 2u[80]-u[79]
        Cb[4] += 2.0f * Cb[5];
        Cb[5]  = 0.0f;
        #pragma unroll
        for (int j = 0; j < 6; ++j) Cc[j] = 0.0f;        // node 80 := BC each step
    }
    if (!act) {
        #pragma unroll
        for (int j = 0; j < 6; ++j) { Ca[j] = 0.f; Cb[j] = 0.f; Cc[j] = 0.f; }
    }

    // ---- time stepping: 5 shuffles + 18 FMAs + 1 select per step ----
    #pragma unroll
    for (int s = 0; s < N_STEPS; ++s) {
        float am = __shfl_up_sync(FULLM, a, 1);    // u[3l-3]
        float bm = __shfl_up_sync(FULLM, b, 1);    // u[3l-2]
        float cm = __shfl_up_sync(FULLM, c, 1);    // u[3l-1]
        float ap = __shfl_down_sync(FULLM, a, 1);  // u[3l+3]
        float bp = __shfl_down_sync(FULLM, b, 1);  // u[3l+4]
        // lane-0 / lane-26 garbage neighbors hit zero coefficients

        e *= E0;

        float na = (fmaf(Ca[0], am, Ca[1] * bm) + fmaf(Ca[2], cm, Ca[3] * a))
                 + fmaf(Ca[4], b, Ca[5] * c);
        float nb = (fmaf(Cb[0], bm, Cb[1] * cm) + fmaf(Cb[2], a, Cb[3] * b))
                 + fmaf(Cb[4], c, Cb[5] * ap);
        float nc = (fmaf(Cc[0], cm, Cc[1] * a) + fmaf(Cc[2], b, Cc[3] * c))
                 + fmaf(Cc[4], ap, Cc[5] * bp);

        a = na;
        b = nb;
        c = is_bc ? fmaf(-50.0f, e, S_R) : nc;     // node 80 = BC(t_{n+1})
    }

    // ---- write result ----
    if (act) {
        out[3 * l]     = a;
        out[3 * l + 1] = b;
        out[3 * l + 2] = c;
    }
}

extern "C" void kernel_launch(void* const* d_in, const int* in_sizes, int n_in,
                              void* d_out, int out_size) {
    (void)in_sizes; (void)n_in; (void)out_size;
    const float* om5 = (const float*)d_in[0];   // omegas5 (80,3)
    const float* om6 = (const float*)d_in[1];   // omegas6 (79,3)
    float* out = (float*)d_out;                 // 81 floats
    weno_bs_kernel<<<1, 32>>>(om5, om6, out);
}

// round 12
// speedup vs baseline: 1.0386x; 1.0386x over previous
#include <cuda_runtime.h>

// WENO Black-Scholes stepper, M=80 (81 nodes), 26 Euler steps.
// Each timestep is affine in u: u_{n+1}[k] = sum_{j=-3}^{+2} C_j[k] * u[k+j],
// with C precomputed once from the fixed WENO weights. Lane l owns nodes
// {3l, 3l+1, 3l+2} (lanes 0..26). Boundary handling folded into coefficients.
// Loop = 5 shuffles + 18 FMAs + 1 select per step, ROLLED (#pragma unroll 1)
// so the ~30-instruction body fits the 6KB L0 I$ instead of ~12.5KB of
// once-through unrolled code (cold I$ fetch was the unexplained ~2K cycles).
// Scalar exp constants precomputed as literals (no prologue MUFU chains
// except the one per-lane init expf).

#define N_STEPS 26
#define FULLM 0xFFFFFFFFu

__global__ void __launch_bounds__(32, 1)
weno_bs_kernel(const float* __restrict__ om5,   // (80,3) row-major
               const float* __restrict__ om6,   // (79,3) row-major
               float* __restrict__ out)         // 81 floats
{
    const int l = threadIdx.x;
    const bool act = (l <= 26);

    // ---- issue all weight loads immediately (overlap memory with init math) ----
    float p[4][3] = {{0}}, r[3][3] = {{0}};
    if (act) {
        #pragma unroll
        for (int j = 0; j < 4; ++j) {
            int row = 3 * l - 1 + j;               // w5 rows 3l-1 .. 3l+2
            if (row >= 0 && row < 80) {
                p[j][0] = om5[3 * row]; p[j][1] = om5[3 * row + 1]; p[j][2] = om5[3 * row + 2];
            }
        }
        #pragma unroll
        for (int j = 0; j < 3; ++j) {
            int row = 3 * l - 1 + j;               // w6 rows 3l-1 .. 3l+1
            if (row >= 0 && row < 79) {
                r[j][0] = om6[3 * row]; r[j][1] = om6[3 * row + 1]; r[j][2] = om6[3 * row + 2];
            }
        }
    }

    const float H     = 0.09375f;                    // exact in fp32
    const float DT    = (float)(1.0 / 26.0);
    const float g1    = DT * 0.055f / H;             // DT*ADV/H
    const float g2    = DT * 0.045f / (H * H);       // DT*0.5*sigma^2/H^2
    const float decay = 1.0f - DT * 0.1f;

    // Precomputed scalar constants (match expf to <1 ulp at fp32):
    const float EH  = 1.0982844232f;                 // e^H,          H=0.09375
    const float E0  = 0.9961612225f;                 // e^{-0.1*DT},  DT=1/26
    const float S_R = 224.0844535f;                  // 50*e^{1.5}

    // ---- init u0 while loads are in flight (one expf chain per lane) ----
    float a = 0.f, b = 0.f, c = 0.f;
    {
        float ea = expf(fmaf((float)(3 * l), H, -6.0f));
        float eb = ea * EH;
        float ec = eb * EH;
        a = fmaxf(fmaf(50.0f, ea, -50.0f), 0.0f);
        b = fmaxf(fmaf(50.0f, eb, -50.0f), 0.0f);
        c = fmaxf(fmaf(50.0f, ec, -50.0f), 0.0f);
        if (!act) { a = b = c = 0.f; }
    }

    float e = 1.0f;
    const bool is_bc = (l == 26);

    // ---- fused per-node 6-tap coefficients (once loads land) ----
    float Ca[6], Cb[6], Cc[6];
    {
        const float i6 = 1.0f / 6.0f;
        #pragma unroll
        for (int n = 0; n < 3; ++n) {
            const float* P = p[n + 1];   // w5 row k
            const float* Q = p[n];       // w5 row k-1
            const float* R = r[n];       // w6 row k-1
            float A_2 = (2.0f * P[0]) * i6;
            float A_1 = (-7.0f * P[0] - P[1]) * i6;
            float A0  = (11.0f * P[0] + 5.0f * P[1] + 2.0f * P[2]) * i6;
            float A1  = (2.0f * P[1] + 5.0f * P[2]) * i6;
            float A2  = (-P[2]) * i6;
            float B_3 = (2.0f * Q[0]) * i6;
            float B_2 = (-7.0f * Q[0] - Q[1]) * i6;
            float B_1 = (11.0f * Q[0] + 5.0f * Q[1] + 2.0f * Q[2]) * i6;
            float B0  = (2.0f * Q[1] + 5.0f * Q[2]) * i6;
            float B1  = (-Q[2]) * i6;
            float C0 = -g1 * B_3;
            float C1 = g1 * (A_2 - B_2) + g2 * R[0];
            float C2 = g1 * (A_1 - B_1) + g2 * (R[1] - 2.0f * R[0]);
            float C3 = g1 * (A0 - B0)   + g2 * (R[0] - 2.0f * R[1] + R[2]) + decay;
            float C4 = g1 * (A1 - B1)   + g2 * (R[1] - 2.0f * R[2]);
            float C5 = g1 * A2          + g2 * R[2];
            float* C = (n == 0) ? Ca : (n == 1) ? Cb : Cc;
            C[0] = C0; C[1] = C1; C[2] = C2; C[3] = C3; C[4] = C4; C[5] = C5;
        }
    }

    // ---- fold boundary conditions into coefficients ----
    if (l == 0) {
        #pragma unroll
        for (int j = 0; j < 6; ++j) Ca[j] = 0.0f;        // node 0 pinned to 0
        Cb[0] = 0.0f; Cb[1] = 0.0f;                      // left ghosts == 0
        Cc[0] = 0.0f;
    }
    if (l == 26) {
        Cb[3] -= Cb[5];                                  // u[81] = 2u[80]-u[79]
        Cb[4] += 2.0f * Cb[5];
        Cb[5]  = 0.0f;
        #pragma unroll
        for (int j = 0; j < 6; ++j) Cc[j] = 0.0f;        // node 80 := BC each step
    }
    if (!act) {
        #pragma unroll
        for (int j = 0; j < 6; ++j) { Ca[j] = 0.f; Cb[j] = 0.f; Cc[j] = 0.f; }
    }

    // ---- time stepping: ROLLED loop, body fits L0 I$ ----
    #pragma unroll 1
    for (int s = 0; s < N_STEPS; ++s) {
        float am = __shfl_up_sync(FULLM, a, 1);    // u[3l-3]
        float bm = __shfl_up_sync(FULLM, b, 1);    // u[3l-2]
        float cm = __shfl_up_sync(FULLM, c, 1);    // u[3l-1]
        float ap = __shfl_down_sync(FULLM, a, 1);  // u[3l+3]
        float bp = __shfl_down_sync(FULLM, b, 1);  // u[3l+4]
        // lane-0 / lane-26 garbage neighbors hit zero coefficients

        e *= E0;

        float na = (fmaf(Ca[0], am, Ca[1] * bm) + fmaf(Ca[2], cm, Ca[3] * a))
                 + fmaf(Ca[4], b, Ca[5] * c);
        float nb = (fmaf(Cb[0], bm, Cb[1] * cm) + fmaf(Cb[2], a, Cb[3] * b))
                 + fmaf(Cb[4], c, Cb[5] * ap);
        float nc = (fmaf(Cc[0], cm, Cc[1] * a) + fmaf(Cc[2], b, Cc[3] * c))
                 + fmaf(Cc[4], ap, Cc[5] * bp);

        a = na;
        b = nb;
        c = is_bc ? fmaf(-50.0f, e, S_R) : nc;     // node 80 = BC(t_{n+1})
    }

    // ---- write result ----
    if (act) {
        out[3 * l]     = a;
        out[3 * l + 1] = b;
        out[3 * l + 2] = c;
    }
}

extern "C" void kernel_launch(void* const* d_in, const int* in_sizes, int n_in,
                              void* d_out, int out_size) {
    (void)in_sizes; (void)n_in; (void)out_size;
    const float* om5 = (const float*)d_in[0];   // omegas5 (80,3)
    const float* om6 = (const float*)d_in[1];   // omegas6 (79,3)
    float* out = (float*)d_out;                 // 81 floats
    weno_bs_kernel<<<1, 32>>>(om5, om6, out);
}